// round 8
// baseline (speedup 1.0000x reference)
#include <cuda_runtime.h>
#include <cuda_fp16.h>

#define Bn 8
#define Qn 128
#define Kn 1024
#define Dn 256
#define Hn 256

// -------- scratch (no allocations allowed) --------
__device__ float  g_WqT[Dn * Hn];
__device__ float  g_WkT[Dn * Hn];
__device__ __half g_qprojH[Bn * Qn * Hn];
__device__ __half g_kprojH[Bn * Kn * Hn];
__device__ __half g_wvH[Hn];
__device__ float  g_scores[Bn * Qn * Kn];   // 4 MB raw scores
__device__ int    g_valid[Bn];

__device__ __forceinline__ __half2 u2h(unsigned u) { __half2 h; *(unsigned*)&h = u; return h; }

// packed fp32x2 FMA (SASS FFMA2): 2 exact IEEE fp32 FMAs per issue
#define FMA2(d, a, b, c) \
    asm("fma.rn.f32x2 %0, %1, %2, %3;" : "=l"(d) : "l"(a), "l"(b), "l"(c))
#define DUP2(d, s) \
    asm("mov.b64 %0, {%1, %1};" : "=l"(d) : "f"(s))
#define PAIR2(d, lo, hi) \
    asm("mov.b64 %0, {%1, %2};" : "=l"(d) : "f"(lo), "f"(hi))
#define UNPAIR2(lo, hi, s) \
    asm("mov.b64 {%0, %1}, %2;" : "=f"(lo), "=f"(hi) : "l"(s))

// ============================================================
// Kernel 0: tiled transpose of W_q/W_k to [D][H] + w_v->half + valid decode.
// ============================================================
__global__ __launch_bounds__(256) void prep_kernel(const float* __restrict__ Wq,
                                                   const float* __restrict__ Wk,
                                                   const float* __restrict__ wv,
                                                   const void*  __restrict__ vlens) {
    __shared__ float tile[32][33];
    int m  = blockIdx.x & 1;
    int t  = blockIdx.x >> 1;          // 0..63
    int d0 = (t & 7) * 32;
    int h0 = (t >> 3) * 32;
    const float* src = m ? Wk : Wq;    // [H][D]
    float*       dst = m ? g_WkT : g_WqT;  // [D][H]
    int lx = threadIdx.x & 31, ly = threadIdx.x >> 5;

    #pragma unroll
    for (int i = 0; i < 32; i += 8)
        tile[ly + i][lx] = src[(size_t)(h0 + ly + i) * Dn + d0 + lx];
    __syncthreads();
    #pragma unroll
    for (int i = 0; i < 32; i += 8)
        dst[(size_t)(d0 + ly + i) * Hn + h0 + lx] = tile[lx][ly + i];

    if (blockIdx.x == 1)
        g_wvH[threadIdx.x] = __float2half_rn(wv[threadIdx.x]);

    if (blockIdx.x == 0 && threadIdx.x == 0) {
        const long long* p64 = (const long long*)vlens;
        const int*       p32 = (const int*)vlens;
        bool ok64 = true;
        for (int i = 0; i < Bn; i++) {
            long long v = p64[i];
            if (v < 0 || v > (long long)Kn) ok64 = false;
        }
        for (int i = 0; i < Bn; i++)
            g_valid[i] = ok64 ? (int)p64[i] : p32[i];
    }
}

// ============================================================
// Kernel 1: projections -> half outputs, fp32x2 packed FFMA2 math.
// Pairing over output h (acc2[r][hp] = (h0,h1) partials): accumulators stay
// 32 regs; a broadcast duplicated via mov.b64 (ALU pipe, hidden under fma).
// grid = 288, block = 256; thread owns 4 h x 8 rows. Masked k-blocks exit.
// ============================================================
__global__ __launch_bounds__(256) void proj_kernel(
        const float* __restrict__ queries,
        const float* __restrict__ keys) {
    __shared__ float s_in[32][Dn];     // 32 KB

    int row0 = blockIdx.x * 32;
    bool is_q = (row0 < Bn * Qn);
    if (!is_q) {
        int rel = row0 - Bn * Qn;
        int b   = rel >> 10;
        int kr0 = rel & (Kn - 1);
        if (kr0 >= g_valid[b]) return;   // whole block masked
    }
    const float* in  = is_q ? (queries + (size_t)row0 * Dn)
                            : (keys + (size_t)(row0 - Bn * Qn) * Dn);
    __half* out      = is_q ? (g_qprojH + (size_t)row0 * Hn)
                            : (g_kprojH + (size_t)(row0 - Bn * Qn) * Hn);
    const float* WT  = is_q ? g_WqT : g_WkT;

    {   // cooperative load of 32 input rows (float4)
        const float4* in4 = (const float4*)in;
        float4* s4 = (float4*)&s_in[0][0];
        #pragma unroll
        for (int i = 0; i < 8; i++)
            s4[threadIdx.x + i * 256] = in4[threadIdx.x + i * 256];
    }
    __syncthreads();

    int hq = threadIdx.x & 63;     // h quad (4 h)
    int rg = threadIdx.x >> 6;     // row group (8 rows)

    unsigned long long acc2[8][2];   // [row][h-pair] packed f32x2
    #pragma unroll
    for (int r = 0; r < 8; r++) { acc2[r][0] = 0ull; acc2[r][1] = 0ull; }

    #pragma unroll 2
    for (int d4 = 0; d4 < 64; d4++) {
        ulonglong2 w2[4];          // per d: (w[h0],w[h1]) , (w[h2],w[h3])
        #pragma unroll
        for (int j = 0; j < 4; j++)
            w2[j] = *(const ulonglong2*)(WT + (size_t)(d4 * 4 + j) * Hn + hq * 4);
        #pragma unroll
        for (int r = 0; r < 8; r++) {
            float4 a = *(const float4*)&s_in[rg * 8 + r][d4 * 4];  // broadcast LDS.128
            #pragma unroll
            for (int j = 0; j < 4; j++) {
                unsigned long long ad;
                DUP2(ad, (&a.x)[j]);
                FMA2(acc2[r][0], ad, w2[j].x, acc2[r][0]);
                FMA2(acc2[r][1], ad, w2[j].y, acc2[r][1]);
            }
        }
    }
    #pragma unroll
    for (int r = 0; r < 8; r++) {
        float a0, a1, a2, a3;
        UNPAIR2(a0, a1, acc2[r][0]);
        UNPAIR2(a2, a3, acc2[r][1]);
        __half2 h01 = __floats2half2_rn(a0, a1);
        __half2 h23 = __floats2half2_rn(a2, a3);
        uint2 u = make_uint2(*(unsigned*)&h01, *(unsigned*)&h23);
        *(uint2*)&out[(size_t)(rg * 8 + r) * Hn + hq * 4] = u;   // STG.64 coalesced
    }
}

// ============================================================
// Kernel 2: scores via tanh.approx.f16x2. grid = 4096 (b, qtile, k-chunk 32);
// early-exit masked chunks. Lane = k; 8 warps = 8 q rows.
// ============================================================
__global__ __launch_bounds__(256, 6) void score_kernel() {
    __shared__ __half2 s_kT2[128 * 33];   // [h2][32 k + pad]
    __shared__ __half2 s_q2[8 * 128];
    __shared__ __half2 s_wv2[128];

    int kc = blockIdx.x & 31;
    int qt = (blockIdx.x >> 5) & 15;
    int b  = blockIdx.x >> 9;
    int L  = g_valid[b];
    int k0 = kc * 32;
    if (k0 >= L) return;               // uniform over block

    int t = threadIdx.x, w = t >> 5, l = t & 31;

    {   // transpose 32 k-rows (half) into s_kT2; conflict-free STS (stride 33)
        int kr = t >> 3, cg = t & 7;
        const uint4* src = (const uint4*)(g_kprojH + ((size_t)b * Kn + k0 + kr) * Hn);
        #pragma unroll
        for (int i = 0; i < 4; i++) {
            uint4 u = src[cg + i * 8];            // 8 halves = 4 h2
            int h2 = (cg + i * 8) * 4;
            s_kT2[(h2 + 0) * 33 + kr] = u2h(u.x);
            s_kT2[(h2 + 1) * 33 + kr] = u2h(u.y);
            s_kT2[(h2 + 2) * 33 + kr] = u2h(u.z);
            s_kT2[(h2 + 3) * 33 + kr] = u2h(u.w);
        }
    }
    {   // q tile: 8 rows x 512 B = 256 uint4
        const uint4* src = (const uint4*)(g_qprojH + ((size_t)b * Qn + qt * 8) * Hn);
        ((uint4*)s_q2)[t] = src[t];
    }
    if (t < 32) ((uint4*)s_wv2)[t] = ((const uint4*)g_wvH)[t];
    __syncthreads();

    const uint4* q4 = (const uint4*)(s_q2 + (size_t)w * 128);
    const uint4* w4 = (const uint4*)s_wv2;
    float accx = 0.f, accy = 0.f;

    #pragma unroll 8
    for (int i = 0; i < 32; i++) {          // 8 h per iter
        uint4 qu = q4[i];                   // broadcast LDS.128 (4 h2)
        uint4 wu = w4[i];                   // broadcast LDS.128
        const __half2* kp = &s_kT2[(size_t)(i * 4) * 33 + l];
        unsigned x0, x1, x2, x3, t0, t1, t2, t3;
        __half2 h;
        h = __hadd2(u2h(qu.x), kp[0 * 33]); x0 = *(unsigned*)&h;
        h = __hadd2(u2h(qu.y), kp[1 * 33]); x1 = *(unsigned*)&h;
        h = __hadd2(u2h(qu.z), kp[2 * 33]); x2 = *(unsigned*)&h;
        h = __hadd2(u2h(qu.w), kp[3 * 33]); x3 = *(unsigned*)&h;
        asm("tanh.approx.f16x2 %0, %1;" : "=r"(t0) : "r"(x0));
        asm("tanh.approx.f16x2 %0, %1;" : "=r"(t1) : "r"(x1));
        asm("tanh.approx.f16x2 %0, %1;" : "=r"(t2) : "r"(x2));
        asm("tanh.approx.f16x2 %0, %1;" : "=r"(t3) : "r"(x3));
        __half2 p0 = __hmul2(u2h(wu.x), u2h(t0));
        __half2 p1 = __hmul2(u2h(wu.y), u2h(t1));
        __half2 p2 = __hmul2(u2h(wu.z), u2h(t2));
        __half2 p3 = __hmul2(u2h(wu.w), u2h(t3));
        __half2 s = __hadd2(__hadd2(p0, p1), __hadd2(p2, p3));
        float2 f = __half22float2(s);       // flush every 8 h -> fp32
        accx += f.x;
        accy += f.y;
    }
    float s = accx + accy;
    int kk = k0 + l;
    if (kk < L)
        g_scores[((size_t)b * Qn + qt * 8 + w) * Kn + kk] = s;   // coalesced STG
}

// ============================================================
// Kernel 3: fused masked softmax + attn @ V.
// grid = 512 (b, qtile, d-chunk of 64); block = 256.
// Stage 8 raw score rows -> per-warp row softmax in smem (redundant per dc,
// cheap) -> AV with packed FFMA2 over k-pairs, 4-way k-split in smem.
// ============================================================
__global__ __launch_bounds__(256) void softav_kernel(
        const float* __restrict__ values,
        float* __restrict__ out) {
    __shared__ float s_attn[8][Kn];       // 32 KB
    __shared__ float s_part[4][8][64];    // 8 KB

    int dc = blockIdx.x & 3;
    int qt = (blockIdx.x >> 2) & 15;
    int b  = blockIdx.x >> 6;
    int L  = g_valid[b];
    int kEff = (L == 0) ? Kn : L;
    int t = threadIdx.x, w = t >> 5, l = t & 31;

    {   // stage 8 raw score rows coalesced
        const float4* src = (const float4*)(g_scores + ((size_t)(b * Qn + qt * 8)) * Kn);
        float4* dst = (float4*)&s_attn[0][0];
        #pragma unroll
        for (int i = 0; i < 8; i++)
            dst[t + i * 256] = src[t + i * 256];
    }
    __syncthreads();

    // ---- per-warp softmax: warp w owns row w (32 elems/lane, stride 32) ----
    {
        float vals[32];
        float m = -3.4e38f;
        #pragma unroll
        for (int i = 0; i < 32; i++) {
            int kk = l + 32 * i;
            float v = (kk < L) ? s_attn[w][kk] : -1e9f;
            vals[i] = v;
            m = fmaxf(m, v);
        }
        #pragma unroll
        for (int o = 16; o > 0; o >>= 1)
            m = fmaxf(m, __shfl_xor_sync(0xffffffffu, m, o));
        float sum = 0.f;
        #pragma unroll
        for (int i = 0; i < 32; i++) {
            float e = __expf(vals[i] - m);   // L==0 -> all 1 -> uniform
            vals[i] = e;
            sum += e;
        }
        #pragma unroll
        for (int o = 16; o > 0; o >>= 1)
            sum += __shfl_xor_sync(0xffffffffu, sum, o);
        float inv = 1.f / sum;
        #pragma unroll
        for (int i = 0; i < 32; i++)
            s_attn[w][l + 32 * i] = vals[i] * inv;
    }
    __syncthreads();

    // ---- AV: thread owns one d, 1/4 of valid k; packed FFMA2 over k-pairs ----
    int dl = t & 63;
    int ks = t >> 6;
    int d  = dc * 64 + dl;
    const float* vb = values + (size_t)b * Kn * Dn + d;

    int kLim = (kEff + 3) & ~3;
    int per  = (((kLim >> 2) + 3) & ~3);
    int kb   = ks * per;
    int ke   = min(kb + per, kLim);

    unsigned long long acc2[8];
    #pragma unroll
    for (int qq = 0; qq < 8; qq++) acc2[qq] = 0ull;

    for (int k = kb; k < ke; k += 4) {
        float v0 = vb[(size_t)(k + 0) * Dn];
        float v1 = vb[(size_t)(k + 1) * Dn];
        float v2 = vb[(size_t)(k + 2) * Dn];
        float v3 = vb[(size_t)(k + 3) * Dn];
        unsigned long long v01, v23;
        PAIR2(v01, v0, v1);
        PAIR2(v23, v2, v3);
        #pragma unroll
        for (int qq = 0; qq < 8; qq++) {
            ulonglong2 a2 = *(const ulonglong2*)&s_attn[qq][k];   // broadcast LDS.128
            FMA2(acc2[qq], a2.x, v01, acc2[qq]);
            FMA2(acc2[qq], a2.y, v23, acc2[qq]);
        }
    }

    #pragma unroll
    for (int qq = 0; qq < 8; qq++) {
        float lo, hi;
        UNPAIR2(lo, hi, acc2[qq]);
        s_part[ks][qq][dl] = lo + hi;
    }
    __syncthreads();

    for (int idx = t; idx < 512; idx += 256) {
        int qq  = idx >> 6;
        int dl2 = idx & 63;
        float s = s_part[0][qq][dl2] + s_part[1][qq][dl2] +
                  s_part[2][qq][dl2] + s_part[3][qq][dl2];
        out[((size_t)(b * Qn + qt * 8 + qq)) * Dn + dc * 64 + dl2] = s;
    }
}

// ============================================================
extern "C" void kernel_launch(void* const* d_in, const int* in_sizes, int n_in,
                              void* d_out, int out_size) {
    const float* queries = (const float*)d_in[0];
    const float* keys    = (const float*)d_in[1];
    const float* values  = (const float*)d_in[2];
    const float* Wq      = (const float*)d_in[3];
    const float* Wk      = (const float*)d_in[4];
    const float* wv      = (const float*)d_in[5];
    const void*  vlens   =               d_in[6];
    float* out = (float*)d_out;

    prep_kernel<<<128, 256>>>(Wq, Wk, wv, vlens);
    proj_kernel<<<(Bn * Qn + Bn * Kn) / 32, 256>>>(queries, keys);
    score_kernel<<<Bn * 16 * 32, 256>>>();
    softav_kernel<<<Bn * 16 * 4, 256>>>(values, out);
}

// round 9
// speedup vs baseline: 1.5451x; 1.5451x over previous
#include <cuda_runtime.h>
#include <cuda_fp16.h>

#define Bn 8
#define Qn 128
#define Kn 1024
#define Dn 256
#define Hn 256

// -------- scratch (no allocations allowed) --------
__device__ float  g_WqT[Dn * Hn];
__device__ float  g_WkT[Dn * Hn];
__device__ __half g_qprojH[Bn * Qn * Hn];
__device__ __half g_kprojH[Bn * Kn * Hn];
__device__ __half g_wvH[Hn];
__device__ float  g_scores[Bn * Qn * Kn];   // 4 MB raw scores
__device__ int    g_valid[Bn];

__device__ __forceinline__ __half2 u2h(unsigned u) { __half2 h; *(unsigned*)&h = u; return h; }

// ============================================================
// Kernel 0: tiled transpose of W_q/W_k to [D][H] + w_v->half + valid decode.
// ============================================================
__global__ __launch_bounds__(256) void prep_kernel(const float* __restrict__ Wq,
                                                   const float* __restrict__ Wk,
                                                   const float* __restrict__ wv,
                                                   const void*  __restrict__ vlens) {
    __shared__ float tile[32][33];
    int m  = blockIdx.x & 1;
    int t  = blockIdx.x >> 1;          // 0..63
    int d0 = (t & 7) * 32;
    int h0 = (t >> 3) * 32;
    const float* src = m ? Wk : Wq;    // [H][D]
    float*       dst = m ? g_WkT : g_WqT;  // [D][H]
    int lx = threadIdx.x & 31, ly = threadIdx.x >> 5;

    #pragma unroll
    for (int i = 0; i < 32; i += 8)
        tile[ly + i][lx] = src[(size_t)(h0 + ly + i) * Dn + d0 + lx];
    __syncthreads();
    #pragma unroll
    for (int i = 0; i < 32; i += 8)
        dst[(size_t)(d0 + ly + i) * Hn + h0 + lx] = tile[lx][ly + i];

    if (blockIdx.x == 1)
        g_wvH[threadIdx.x] = __float2half_rn(wv[threadIdx.x]);

    if (blockIdx.x == 0 && threadIdx.x == 0) {
        const long long* p64 = (const long long*)vlens;
        const int*       p32 = (const int*)vlens;
        bool ok64 = true;
        for (int i = 0; i < Bn; i++) {
            long long v = p64[i];
            if (v < 0 || v > (long long)Kn) ok64 = false;
        }
        for (int i = 0; i < Bn; i++)
            g_valid[i] = ok64 ? (int)p64[i] : p32[i];
    }
}

// ============================================================
// Kernel 1: projections -> half outputs, scalar fp32 FFMA (R6 form).
// grid = 288, block = 256; thread owns 4 h x 8 rows. Masked k-blocks exit.
// ============================================================
__global__ __launch_bounds__(256) void proj_kernel(
        const float* __restrict__ queries,
        const float* __restrict__ keys) {
    __shared__ float s_in[32][Dn];     // 32 KB

    int row0 = blockIdx.x * 32;
    bool is_q = (row0 < Bn * Qn);
    if (!is_q) {
        int rel = row0 - Bn * Qn;
        int b   = rel >> 10;
        int kr0 = rel & (Kn - 1);
        if (kr0 >= g_valid[b]) return;   // whole block masked
    }
    const float* in  = is_q ? (queries + (size_t)row0 * Dn)
                            : (keys + (size_t)(row0 - Bn * Qn) * Dn);
    __half* out      = is_q ? (g_qprojH + (size_t)row0 * Hn)
                            : (g_kprojH + (size_t)(row0 - Bn * Qn) * Hn);
    const float* WT  = is_q ? g_WqT : g_WkT;

    {   // cooperative load of 32 input rows (float4)
        const float4* in4 = (const float4*)in;
        float4* s4 = (float4*)&s_in[0][0];
        #pragma unroll
        for (int i = 0; i < 8; i++)
            s4[threadIdx.x + i * 256] = in4[threadIdx.x + i * 256];
    }
    __syncthreads();

    int hq = threadIdx.x & 63;     // h quad (4 h)
    int rg = threadIdx.x >> 6;     // row group (8 rows)

    float acc[8][4];
    #pragma unroll
    for (int r = 0; r < 8; r++)
        #pragma unroll
        for (int j = 0; j < 4; j++) acc[r][j] = 0.f;

    const float4* wt4 = (const float4*)WT;   // [d][64 quads]
    #pragma unroll 2
    for (int d4 = 0; d4 < 64; d4++) {
        float4 w[4];
        #pragma unroll
        for (int j = 0; j < 4; j++)
            w[j] = wt4[(size_t)(d4 * 4 + j) * 64 + hq];   // coalesced LDG.128
        #pragma unroll
        for (int r = 0; r < 8; r++) {
            float4 a = *(const float4*)&s_in[rg * 8 + r][d4 * 4];  // broadcast LDS.128
            #pragma unroll
            for (int j = 0; j < 4; j++) {
                float av = (&a.x)[j];
                acc[r][0] = fmaf(av, w[j].x, acc[r][0]);
                acc[r][1] = fmaf(av, w[j].y, acc[r][1]);
                acc[r][2] = fmaf(av, w[j].z, acc[r][2]);
                acc[r][3] = fmaf(av, w[j].w, acc[r][3]);
            }
        }
    }
    #pragma unroll
    for (int r = 0; r < 8; r++) {
        __half2 h01 = __floats2half2_rn(acc[r][0], acc[r][1]);
        __half2 h23 = __floats2half2_rn(acc[r][2], acc[r][3]);
        uint2 u = make_uint2(*(unsigned*)&h01, *(unsigned*)&h23);
        *(uint2*)&out[(size_t)(rg * 8 + r) * Hn + hq * 4] = u;   // STG.64 coalesced
    }
}

// ============================================================
// Kernel 2: scores via tanh.approx.f16x2 (R6 form). grid = 4096 blocks
// (b, qtile, k-chunk 32); early-exit masked. Lane = k; 8 warps = 8 q rows.
// ============================================================
__global__ __launch_bounds__(256, 6) void score_kernel() {
    __shared__ __half2 s_kT2[128 * 33];   // [h2][32 k + pad]
    __shared__ __half2 s_q2[8 * 128];
    __shared__ __half2 s_wv2[128];

    int kc = blockIdx.x & 31;
    int qt = (blockIdx.x >> 5) & 15;
    int b  = blockIdx.x >> 9;
    int L  = g_valid[b];
    int k0 = kc * 32;
    if (k0 >= L) return;               // uniform over block

    int t = threadIdx.x, w = t >> 5, l = t & 31;

    {   // transpose 32 k-rows (half) into s_kT2; conflict-free STS (stride 33)
        int kr = t >> 3, cg = t & 7;
        const uint4* src = (const uint4*)(g_kprojH + ((size_t)b * Kn + k0 + kr) * Hn);
        #pragma unroll
        for (int i = 0; i < 4; i++) {
            uint4 u = src[cg + i * 8];            // 8 halves = 4 h2
            int h2 = (cg + i * 8) * 4;
            s_kT2[(h2 + 0) * 33 + kr] = u2h(u.x);
            s_kT2[(h2 + 1) * 33 + kr] = u2h(u.y);
            s_kT2[(h2 + 2) * 33 + kr] = u2h(u.z);
            s_kT2[(h2 + 3) * 33 + kr] = u2h(u.w);
        }
    }
    {   // q tile: 8 rows x 512 B = 256 uint4
        const uint4* src = (const uint4*)(g_qprojH + ((size_t)b * Qn + qt * 8) * Hn);
        ((uint4*)s_q2)[t] = src[t];
    }
    if (t < 32) ((uint4*)s_wv2)[t] = ((const uint4*)g_wvH)[t];
    __syncthreads();

    const uint4* q4 = (const uint4*)(s_q2 + (size_t)w * 128);
    const uint4* w4 = (const uint4*)s_wv2;
    float accx = 0.f, accy = 0.f;

    #pragma unroll 8
    for (int i = 0; i < 32; i++) {          // 8 h per iter
        uint4 qu = q4[i];                   // broadcast LDS.128 (4 h2)
        uint4 wu = w4[i];                   // broadcast LDS.128
        const __half2* kp = &s_kT2[(size_t)(i * 4) * 33 + l];
        unsigned x0, x1, x2, x3, t0, t1, t2, t3;
        __half2 h;
        h = __hadd2(u2h(qu.x), kp[0 * 33]); x0 = *(unsigned*)&h;
        h = __hadd2(u2h(qu.y), kp[1 * 33]); x1 = *(unsigned*)&h;
        h = __hadd2(u2h(qu.z), kp[2 * 33]); x2 = *(unsigned*)&h;
        h = __hadd2(u2h(qu.w), kp[3 * 33]); x3 = *(unsigned*)&h;
        asm("tanh.approx.f16x2 %0, %1;" : "=r"(t0) : "r"(x0));
        asm("tanh.approx.f16x2 %0, %1;" : "=r"(t1) : "r"(x1));
        asm("tanh.approx.f16x2 %0, %1;" : "=r"(t2) : "r"(x2));
        asm("tanh.approx.f16x2 %0, %1;" : "=r"(t3) : "r"(x3));
        __half2 p0 = __hmul2(u2h(wu.x), u2h(t0));
        __half2 p1 = __hmul2(u2h(wu.y), u2h(t1));
        __half2 p2 = __hmul2(u2h(wu.z), u2h(t2));
        __half2 p3 = __hmul2(u2h(wu.w), u2h(t3));
        __half2 s = __hadd2(__hadd2(p0, p1), __hadd2(p2, p3));
        float2 f = __half22float2(s);       // flush every 8 h -> fp32
        accx += f.x;
        accy += f.y;
    }
    float s = accx + accy;
    int kk = k0 + l;
    if (kk < L)
        g_scores[((size_t)b * Qn + qt * 8 + w) * Kn + kk] = s;   // coalesced STG
}

// ============================================================
// Kernel 3: fused masked softmax (ONCE) + attn @ V.
// grid = B*16 = 128 (b, qtile); block = 1024 (32 warps).
// Softmax: 4 warps per q row, vals[8]/lane (register-light).
// AV: thread = (d 0..255, k-slice 0..3); partials reuse s_attn smem.
// ============================================================
__global__ __launch_bounds__(1024) void softav_kernel(
        const float* __restrict__ values,
        float* __restrict__ out) {
    __shared__ float s_attn[8][Kn];       // 32 KB (scores -> attn -> partials)
    __shared__ float s_max[32];
    __shared__ float s_sum[32];

    int qt = blockIdx.x & 15;
    int b  = blockIdx.x >> 4;
    int L  = g_valid[b];
    int kEff = (L == 0) ? Kn : L;
    int t = threadIdx.x, w = t >> 5, l = t & 31;

    {   // stage 8 raw score rows coalesced (2048 float4, 2 per thread)
        const float4* src = (const float4*)(g_scores + ((size_t)(b * Qn + qt * 8)) * Kn);
        float4* dst = (float4*)&s_attn[0][0];
        dst[t]        = src[t];
        dst[t + 1024] = src[t + 1024];
    }
    __syncthreads();

    // ---- softmax: warp w -> row r = w>>2, quarter = w&3 ----
    int r = w >> 2;
    int base = (w & 3) * 256 + l;
    float vals[8];
    {
        float m = -3.4e38f;
        #pragma unroll
        for (int i = 0; i < 8; i++) {
            int kk = base + 32 * i;
            float v = (kk < L) ? s_attn[r][kk] : -1e9f;
            vals[i] = v;
            m = fmaxf(m, v);
        }
        #pragma unroll
        for (int o = 16; o > 0; o >>= 1)
            m = fmaxf(m, __shfl_xor_sync(0xffffffffu, m, o));
        if (l == 0) s_max[w] = m;
        __syncthreads();
        m = fmaxf(fmaxf(s_max[r * 4 + 0], s_max[r * 4 + 1]),
                  fmaxf(s_max[r * 4 + 2], s_max[r * 4 + 3]));

        float sum = 0.f;
        #pragma unroll
        for (int i = 0; i < 8; i++) {
            float e = __expf(vals[i] - m);   // L==0 -> all 1 -> uniform 1/1024
            vals[i] = e;
            sum += e;
        }
        #pragma unroll
        for (int o = 16; o > 0; o >>= 1)
            sum += __shfl_xor_sync(0xffffffffu, sum, o);
        if (l == 0) s_sum[w] = sum;
        __syncthreads();
        float inv = 1.f / (s_sum[r * 4 + 0] + s_sum[r * 4 + 1] +
                           s_sum[r * 4 + 2] + s_sum[r * 4 + 3]);
        #pragma unroll
        for (int i = 0; i < 8; i++)
            s_attn[r][base + 32 * i] = vals[i] * inv;
    }
    __syncthreads();

    // ---- AV: thread owns one d, 1/4 of valid k ----
    int dl = t & 255;
    int ks = t >> 8;
    const float* vb = values + (size_t)b * Kn * Dn + dl;

    int kLim = (kEff + 3) & ~3;
    int per  = (((kLim >> 2) + 3) & ~3);       // per-slice span, multiple of 4
    int kb   = ks * per;
    int ke   = min(kb + per, kLim);

    float acc[8];
    #pragma unroll
    for (int qq = 0; qq < 8; qq++) acc[qq] = 0.f;

    for (int k = kb; k < ke; k += 4) {
        float v0 = vb[(size_t)(k + 0) * Dn];
        float v1 = vb[(size_t)(k + 1) * Dn];
        float v2 = vb[(size_t)(k + 2) * Dn];
        float v3 = vb[(size_t)(k + 3) * Dn];
        #pragma unroll
        for (int qq = 0; qq < 8; qq++) {
            float4 a = *(const float4*)&s_attn[qq][k];   // broadcast LDS.128
            acc[qq] = fmaf(a.x, v0, acc[qq]);
            acc[qq] = fmaf(a.y, v1, acc[qq]);
            acc[qq] = fmaf(a.z, v2, acc[qq]);
            acc[qq] = fmaf(a.w, v3, acc[qq]);
        }
    }

    __syncthreads();                       // all reads of s_attn done
    float* part = &s_attn[0][0];           // reuse as [ks 4][qq 8][dl 256]
    #pragma unroll
    for (int qq = 0; qq < 8; qq++)
        part[((ks * 8 + qq) << 8) + dl] = acc[qq];
    __syncthreads();

    for (int idx = t; idx < 2048; idx += 1024) {
        int qq  = idx >> 8;
        int dl2 = idx & 255;
        float s = part[((0 * 8 + qq) << 8) + dl2] + part[((1 * 8 + qq) << 8) + dl2] +
                  part[((2 * 8 + qq) << 8) + dl2] + part[((3 * 8 + qq) << 8) + dl2];
        out[((size_t)(b * Qn + qt * 8 + qq)) * Dn + dl2] = s;
    }
}

// ============================================================
extern "C" void kernel_launch(void* const* d_in, const int* in_sizes, int n_in,
                              void* d_out, int out_size) {
    const float* queries = (const float*)d_in[0];
    const float* keys    = (const float*)d_in[1];
    const float* values  = (const float*)d_in[2];
    const float* Wq      = (const float*)d_in[3];
    const float* Wk      = (const float*)d_in[4];
    const float* wv      = (const float*)d_in[5];
    const void*  vlens   =               d_in[6];
    float* out = (float*)d_out;

    prep_kernel<<<128, 256>>>(Wq, Wk, wv, vlens);
    proj_kernel<<<(Bn * Qn + Bn * Kn) / 32, 256>>>(queries, keys);
    score_kernel<<<Bn * 16 * 32, 256>>>();
    softav_kernel<<<Bn * 16, 1024>>>(values, out);
}